// round 3
// baseline (speedup 1.0000x reference)
#include <cuda_runtime.h>
#include <math.h>

#define BB 64
#define SS 1024
#define DK 128
#define DV 128

// Normalized keys (32 MB) + adjacent-key dots c[s] = kn[s-1]·kn[s] (256 KB).
__device__ float g_kn[(size_t)BB * SS * DK];
__device__ float g_c[BB * SS];

// ---------------------------------------------------------------------------
// Pre-pass (fully parallel): normalize keys, compute adjacent normalized dots.
// One warp per (b,s) row; loads row s and row s-1, three fused shfl reductions.
// ---------------------------------------------------------------------------
__global__ void prep_kernel(const float* __restrict__ key) {
    int row = blockIdx.x * 8 + (threadIdx.x >> 5);
    int lane = threadIdx.x & 31;
    if (row >= BB * SS) return;
    int s = row & (SS - 1);

    float4 kv = reinterpret_cast<const float4*>(key)[(size_t)row * 32 + lane];
    float nn = kv.x * kv.x + kv.y * kv.y + kv.z * kv.z + kv.w * kv.w;
    float np = 0.f, dd = 0.f;
    if (s > 0) {
        float4 kp = reinterpret_cast<const float4*>(key)[(size_t)(row - 1) * 32 + lane];
        np = kp.x * kp.x + kp.y * kp.y + kp.z * kp.z + kp.w * kp.w;
        dd = kv.x * kp.x + kv.y * kp.y + kv.z * kp.z + kv.w * kp.w;
    }
    #pragma unroll
    for (int o = 16; o; o >>= 1) {
        nn += __shfl_xor_sync(0xffffffffu, nn, o);
        np += __shfl_xor_sync(0xffffffffu, np, o);
        dd += __shfl_xor_sync(0xffffffffu, dd, o);
    }
    float invn = 1.0f / (sqrtf(nn) + 1e-6f);
    float4 o4 = make_float4(kv.x * invn, kv.y * invn, kv.z * invn, kv.w * invn);
    reinterpret_cast<float4*>(g_kn)[(size_t)row * 32 + lane] = o4;
    if (lane == 0)
        g_c[row] = (s > 0) ? dd * invn * (1.0f / (sqrtf(np) + 1e-6f)) : 0.0f;
}

// ---------------------------------------------------------------------------
// Packed f32x2 helpers (sm_100a-family FFMA2 via PTX)
// ---------------------------------------------------------------------------
__device__ __forceinline__ unsigned long long pack2(float x) {
    unsigned long long r;
    asm("mov.b64 %0, {%1, %1};" : "=l"(r) : "f"(x));
    return r;
}
__device__ __forceinline__ void fma2(unsigned long long& d,
                                     unsigned long long a, unsigned long long b) {
    asm("fma.rn.f32x2 %0, %1, %2, %0;" : "+l"(d) : "l"(a), "l"(b));
}
__device__ __forceinline__ float sum2(unsigned long long a) {
    float lo, hi;
    asm("mov.b64 {%0, %1}, %2;" : "=f"(lo), "=f"(hi) : "l"(a));
    return lo + hi;
}

// ---------------------------------------------------------------------------
// Sequential scan, one CTA per batch, 128 threads, row t of memory in regs
// (64 packed f32x2). One-step-deferred update decouples gate chain from GEMV.
// ---------------------------------------------------------------------------
__global__ __launch_bounds__(128, 1) void sgm_kernel(
    const float* __restrict__ memory,
    const float* __restrict__ value,
    float* __restrict__ out)
{
    const int b = blockIdx.x;
    const int t = threadIdx.x;
    const int lane = t & 31;
    const int wid = t >> 5;

    __shared__ __align__(16) float sk[3][DK];
    __shared__ float red[2][4];

    const float* knb = g_kn + (size_t)b * SS * DK;
    const float* vb  = value + (size_t)b * SS * DV;
    const float* cb  = g_c + (size_t)b * SS;
    float* gates = out + (size_t)BB * DV * DK + (size_t)b * SS;

    // Load memory row t as 64 packed f32x2.
    unsigned long long m2[DK / 2];
    {
        const ulonglong2* mb = reinterpret_cast<const ulonglong2*>(
            memory + (size_t)b * DV * DK + (size_t)t * DK);
        #pragma unroll
        for (int j = 0; j < DK / 4; ++j) {
            ulonglong2 x = mb[j];
            m2[2 * j] = x.x; m2[2 * j + 1] = x.y;
        }
    }

    // ---- prologue: step 0 ----
    sk[0][t] = knb[t];
    float vs = vb[t];
    float ccur = cb[1];           // c for step 1 (uniform load)
    __syncthreads();

    float pprev, sprev;
    {
        const ulonglong2* kc = reinterpret_cast<const ulonglong2*>(&sk[0][0]);
        unsigned long long a0 = 0, a1 = 0, a2 = 0, a3 = 0;
        #pragma unroll
        for (int j = 0; j < 16; ++j) {
            ulonglong2 k0 = kc[2 * j], k1 = kc[2 * j + 1];
            fma2(a0, m2[4 * j + 0], k0.x);
            fma2(a1, m2[4 * j + 1], k0.y);
            fma2(a2, m2[4 * j + 2], k1.x);
            fma2(a3, m2[4 * j + 3], k1.y);
        }
        float pred = (sum2(a0) + sum2(a1)) + (sum2(a2) + sum2(a3));
        float sur = pred - vs;
        float ss2 = sur * sur;
        #pragma unroll
        for (int o = 16; o; o >>= 1) ss2 += __shfl_xor_sync(0xffffffffu, ss2, o);
        if (lane == 0) red[0][wid] = ss2;
        pprev = pred; sprev = sur;
    }
    // prefetch step 1
    sk[1][t] = knb[DK + t];
    vs = vb[DV + t];
    __syncthreads();

    // Buffer roles entering iteration s: ip -> k_n[s-1], ic -> k_n[s], inx free.
    int ip = 2, ic = 0, inx = 1;   // will rotate at loop top: ip=0, ic=1, inx=2

    for (int s = 1; s < SS; ++s) {
        { int tmp = ip; ip = ic; ic = inx; inx = tmp; }

        const int sn = (s + 1 < SS) ? s + 1 : s;
        float knxt = knb[(size_t)sn * DK + t];
        float vnxt = vb[(size_t)sn * DV + t];
        float cnxt = cb[sn];

        // A: D[t] = m_{s-2}[t,:] · k_n[s]   (independent of step s-1 gate)
        const ulonglong2* kc = reinterpret_cast<const ulonglong2*>(&sk[ic][0]);
        unsigned long long a0 = 0, a1 = 0, a2 = 0, a3 = 0;
        #pragma unroll
        for (int j = 0; j < 16; ++j) {
            ulonglong2 k0 = kc[2 * j], k1 = kc[2 * j + 1];
            fma2(a0, m2[4 * j + 0], k0.x);
            fma2(a1, m2[4 * j + 1], k0.y);
            fma2(a2, m2[4 * j + 2], k1.x);
            fma2(a3, m2[4 * j + 3], k1.y);
        }

        // B: finalize gate for step s-1
        const float* rp = red[(s - 1) & 1];
        float tot = (rp[0] + rp[1]) + (rp[2] + rp[3]);
        float snorm = sqrtf(tot);
        float gate = 1.0f / (1.0f + __expf((0.1f - snorm) * 10.0f));
        if (t == 0) gates[s - 1] = gate;
        float u = gate * fmaf(0.1f, sprev, pprev);

        // C: apply deferred rank-1 update: m -= u * k_n[s-1]
        unsigned long long nu = pack2(-u);
        const ulonglong2* kp = reinterpret_cast<const ulonglong2*>(&sk[ip][0]);
        #pragma unroll
        for (int j = 0; j < 16; ++j) {
            ulonglong2 k0 = kp[2 * j], k1 = kp[2 * j + 1];
            fma2(m2[4 * j + 0], k0.x, nu);
            fma2(m2[4 * j + 1], k0.y, nu);
            fma2(m2[4 * j + 2], k1.x, nu);
            fma2(m2[4 * j + 3], k1.y, nu);
        }

        // D: pred_s with deferred correction, surprise, start reduce
        float pred = ((sum2(a0) + sum2(a1)) + (sum2(a2) + sum2(a3))) - u * ccur;
        float sur = pred - vs;
        float ss2 = sur * sur;
        #pragma unroll
        for (int o = 16; o; o >>= 1) ss2 += __shfl_xor_sync(0xffffffffu, ss2, o);
        if (lane == 0) red[s & 1][wid] = ss2;

        pprev = pred; sprev = sur; vs = vnxt; ccur = cnxt;
        sk[inx][t] = knxt;
        __syncthreads();
    }

    // ---- epilogue: gate + update for step SS-1 ----
    {
        const float* rp = red[(SS - 1) & 1];
        float tot = (rp[0] + rp[1]) + (rp[2] + rp[3]);
        float snorm = sqrtf(tot);
        float gate = 1.0f / (1.0f + __expf((0.1f - snorm) * 10.0f));
        if (t == 0) gates[SS - 1] = gate;
        float u = gate * fmaf(0.1f, sprev, pprev);
        unsigned long long nu = pack2(-u);
        const ulonglong2* kp = reinterpret_cast<const ulonglong2*>(&sk[ic][0]);
        #pragma unroll
        for (int j = 0; j < 16; ++j) {
            ulonglong2 k0 = kp[2 * j], k1 = kp[2 * j + 1];
            fma2(m2[4 * j + 0], k0.x, nu);
            fma2(m2[4 * j + 1], k0.y, nu);
            fma2(m2[4 * j + 2], k1.x, nu);
            fma2(m2[4 * j + 3], k1.y, nu);
        }
    }

    // Store final memory.
    {
        ulonglong2* ob = reinterpret_cast<ulonglong2*>(
            out + (size_t)b * DV * DK + (size_t)t * DK);
        #pragma unroll
        for (int j = 0; j < DK / 4; ++j) {
            ulonglong2 x;
            x.x = m2[2 * j]; x.y = m2[2 * j + 1];
            ob[j] = x;
        }
    }
}

extern "C" void kernel_launch(void* const* d_in, const int* in_sizes, int n_in,
                              void* d_out, int out_size) {
    const float* memory = (const float*)d_in[0];
    const float* key    = (const float*)d_in[1];
    const float* value  = (const float*)d_in[2];
    float* out = (float*)d_out;

    prep_kernel<<<(BB * SS) / 8, 256>>>(key);
    sgm_kernel<<<BB, 128>>>(memory, value, out);
}

// round 4
// speedup vs baseline: 1.3346x; 1.3346x over previous
#include <cuda_runtime.h>
#include <math.h>

#define BB 64
#define SS 1024
#define DK 128
#define DV 128
#define HALF 64
#define KST 68   // padded half-stride (floats); 68*4B keeps 16B align, shifts banks by 4

// Normalized keys (32 MB) + adjacent-key dots c[s] = kn[s-1]·kn[s] (256 KB).
__device__ float g_kn[(size_t)BB * SS * DK];
__device__ float g_c[BB * SS];

// ---------------------------------------------------------------------------
// Pre-pass (fully parallel): normalize keys, adjacent normalized dots.
// ---------------------------------------------------------------------------
__global__ void prep_kernel(const float* __restrict__ key) {
    int row = blockIdx.x * 8 + (threadIdx.x >> 5);
    int lane = threadIdx.x & 31;
    if (row >= BB * SS) return;
    int s = row & (SS - 1);

    float4 kv = reinterpret_cast<const float4*>(key)[(size_t)row * 32 + lane];
    float nn = kv.x * kv.x + kv.y * kv.y + kv.z * kv.z + kv.w * kv.w;
    float np = 0.f, dd = 0.f;
    if (s > 0) {
        float4 kp = reinterpret_cast<const float4*>(key)[(size_t)(row - 1) * 32 + lane];
        np = kp.x * kp.x + kp.y * kp.y + kp.z * kp.z + kp.w * kp.w;
        dd = kv.x * kp.x + kv.y * kp.y + kv.z * kp.z + kv.w * kp.w;
    }
    #pragma unroll
    for (int o = 16; o; o >>= 1) {
        nn += __shfl_xor_sync(0xffffffffu, nn, o);
        np += __shfl_xor_sync(0xffffffffu, np, o);
        dd += __shfl_xor_sync(0xffffffffu, dd, o);
    }
    float invn = 1.0f / (sqrtf(nn) + 1e-6f);
    float4 o4 = make_float4(kv.x * invn, kv.y * invn, kv.z * invn, kv.w * invn);
    reinterpret_cast<float4*>(g_kn)[(size_t)row * 32 + lane] = o4;
    if (lane == 0)
        g_c[row] = (s > 0) ? dd * invn * (1.0f / (sqrtf(np) + 1e-6f)) : 0.0f;
}

// ---------------------------------------------------------------------------
// Packed f32x2 helpers
// ---------------------------------------------------------------------------
__device__ __forceinline__ unsigned long long pack2(float x) {
    unsigned long long r;
    asm("mov.b64 %0, {%1, %1};" : "=l"(r) : "f"(x));
    return r;
}
__device__ __forceinline__ void fma2(unsigned long long& d,
                                     unsigned long long a, unsigned long long b) {
    asm("fma.rn.f32x2 %0, %1, %2, %0;" : "+l"(d) : "l"(a), "l"(b));
}
__device__ __forceinline__ float sum2(unsigned long long a) {
    float lo, hi;
    asm("mov.b64 {%0, %1}, %2;" : "=f"(lo), "=f"(hi) : "l"(a));
    return lo + hi;
}

// ---------------------------------------------------------------------------
// Sequential scan: one CTA per batch, 256 threads. Thread (r=t>>1, h=t&1)
// owns 64 floats of memory row r (32 f32x2 regs). Full dot recovered with
// one shfl_xor(1). One-step-deferred rank-1 update. 2 warps/SMSP.
// ---------------------------------------------------------------------------
__global__ __launch_bounds__(256, 1) void sgm_kernel(
    const float* __restrict__ memory,
    const float* __restrict__ value,
    float* __restrict__ out)
{
    const int b = blockIdx.x;
    const int t = threadIdx.x;
    const int r = t >> 1;
    const int h = t & 1;
    const int lane = t & 31;
    const int wid = t >> 5;

    __shared__ __align__(16) float sk[3][2 * KST];
    __shared__ float red[2][8];

    const float* knb = g_kn + (size_t)b * SS * DK;
    const float* vb  = value + (size_t)b * SS * DV;
    const float* cb  = g_c + (size_t)b * SS;
    float* gates = out + (size_t)BB * DV * DK + (size_t)b * SS;

    // Load my 64-float half of memory row r as 32 packed f32x2.
    unsigned long long m2[HALF / 2];
    {
        const ulonglong2* mb = reinterpret_cast<const ulonglong2*>(
            memory + (size_t)b * DV * DK + (size_t)r * DK + h * HALF);
        #pragma unroll
        for (int j = 0; j < HALF / 4; ++j) {
            ulonglong2 x = mb[j];
            m2[2 * j] = x.x; m2[2 * j + 1] = x.y;
        }
    }

    // ---- prologue: stage k0, compute step-0 dot/reduce ----
    if (t < DK) sk[0][(t >> 6) * KST + (t & 63)] = knb[t];
    float vs = vb[r];
    float ccur = cb[1];
    __syncthreads();

    float pprev, sprev;
    {
        const ulonglong2* kc = reinterpret_cast<const ulonglong2*>(&sk[0][h * KST]);
        unsigned long long a0 = 0, a1 = 0, a2 = 0, a3 = 0;
        #pragma unroll
        for (int j = 0; j < 4; ++j) {
            ulonglong2 k0 = kc[4 * j], k1 = kc[4 * j + 1];
            ulonglong2 k2 = kc[4 * j + 2], k3 = kc[4 * j + 3];
            fma2(a0, m2[8 * j + 0], k0.x); fma2(a1, m2[8 * j + 1], k0.y);
            fma2(a2, m2[8 * j + 2], k1.x); fma2(a3, m2[8 * j + 3], k1.y);
            fma2(a0, m2[8 * j + 4], k2.x); fma2(a1, m2[8 * j + 5], k2.y);
            fma2(a2, m2[8 * j + 6], k3.x); fma2(a3, m2[8 * j + 7], k3.y);
        }
        float part = (sum2(a0) + sum2(a1)) + (sum2(a2) + sum2(a3));
        float pred = part + __shfl_xor_sync(0xffffffffu, part, 1);
        float sur = pred - vs;
        float ss2 = 0.5f * sur * sur;            // pairs duplicate -> halve
        #pragma unroll
        for (int o = 16; o; o >>= 1) ss2 += __shfl_xor_sync(0xffffffffu, ss2, o);
        if (lane == 0) red[0][wid] = ss2;
        pprev = pred; sprev = sur;
    }
    if (t < DK) sk[1][(t >> 6) * KST + (t & 63)] = knb[DK + t];
    vs = vb[DV + r];
    __syncthreads();

    int ip = 2, ic = 0, inx = 1;  // rotate at loop top -> ip=0(kn[s-1]), ic=1(kn[s])

    for (int s = 1; s < SS; ++s) {
        { int tmp = ip; ip = ic; ic = inx; inx = tmp; }

        const int sn = (s + 1 < SS) ? s + 1 : s;
        float knxt = (t < DK) ? knb[(size_t)sn * DK + t] : 0.0f;
        float vnxt = vb[(size_t)sn * DV + r];
        float cnxt = cb[sn];

        // A: partial dot D = m_{s-2}[r, h-half] · kn[s]  (gate-independent)
        const ulonglong2* kc = reinterpret_cast<const ulonglong2*>(&sk[ic][h * KST]);
        unsigned long long a0 = 0, a1 = 0, a2 = 0, a3 = 0;
        #pragma unroll
        for (int j = 0; j < 4; ++j) {
            ulonglong2 k0 = kc[4 * j], k1 = kc[4 * j + 1];
            ulonglong2 k2 = kc[4 * j + 2], k3 = kc[4 * j + 3];
            fma2(a0, m2[8 * j + 0], k0.x); fma2(a1, m2[8 * j + 1], k0.y);
            fma2(a2, m2[8 * j + 2], k1.x); fma2(a3, m2[8 * j + 3], k1.y);
            fma2(a0, m2[8 * j + 4], k2.x); fma2(a1, m2[8 * j + 5], k2.y);
            fma2(a2, m2[8 * j + 6], k3.x); fma2(a3, m2[8 * j + 7], k3.y);
        }

        // B: finalize gate of step s-1
        const float* rp = red[(s - 1) & 1];
        float tot = ((rp[0] + rp[1]) + (rp[2] + rp[3]))
                  + ((rp[4] + rp[5]) + (rp[6] + rp[7]));
        float snorm = sqrtf(tot);
        float gate = 1.0f / (1.0f + __expf((0.1f - snorm) * 10.0f));
        if (t == 0) gates[s - 1] = gate;
        float u = gate * fmaf(0.1f, sprev, pprev);

        // C: deferred rank-1 update m -= u * kn[s-1]
        unsigned long long nu = pack2(-u);
        const ulonglong2* kp = reinterpret_cast<const ulonglong2*>(&sk[ip][h * KST]);
        #pragma unroll
        for (int j = 0; j < 4; ++j) {
            ulonglong2 k0 = kp[4 * j], k1 = kp[4 * j + 1];
            ulonglong2 k2 = kp[4 * j + 2], k3 = kp[4 * j + 3];
            fma2(m2[8 * j + 0], k0.x, nu); fma2(m2[8 * j + 1], k0.y, nu);
            fma2(m2[8 * j + 2], k1.x, nu); fma2(m2[8 * j + 3], k1.y, nu);
            fma2(m2[8 * j + 4], k2.x, nu); fma2(m2[8 * j + 5], k2.y, nu);
            fma2(m2[8 * j + 6], k3.x, nu); fma2(m2[8 * j + 7], k3.y, nu);
        }

        // D: assemble pred_s (with deferred correction), surprise, reduce
        float part = (sum2(a0) + sum2(a1)) + (sum2(a2) + sum2(a3));
        float pred = (part + __shfl_xor_sync(0xffffffffu, part, 1)) - u * ccur;
        float sur = pred - vs;
        float ss2 = 0.5f * sur * sur;
        #pragma unroll
        for (int o = 16; o; o >>= 1) ss2 += __shfl_xor_sync(0xffffffffu, ss2, o);
        if (lane == 0) red[s & 1][wid] = ss2;

        pprev = pred; sprev = sur; vs = vnxt; ccur = cnxt;
        if (t < DK) sk[inx][(t >> 6) * KST + (t & 63)] = knxt;
        __syncthreads();
    }

    // ---- epilogue: gate + update for step SS-1 (kn[SS-1] is in sk[ic]) ----
    {
        const float* rp = red[(SS - 1) & 1];
        float tot = ((rp[0] + rp[1]) + (rp[2] + rp[3]))
                  + ((rp[4] + rp[5]) + (rp[6] + rp[7]));
        float snorm = sqrtf(tot);
        float gate = 1.0f / (1.0f + __expf((0.1f - snorm) * 10.0f));
        if (t == 0) gates[SS - 1] = gate;
        float u = gate * fmaf(0.1f, sprev, pprev);
        unsigned long long nu = pack2(-u);
        const ulonglong2* kp = reinterpret_cast<const ulonglong2*>(&sk[ic][h * KST]);
        #pragma unroll
        for (int j = 0; j < 4; ++j) {
            ulonglong2 k0 = kp[4 * j], k1 = kp[4 * j + 1];
            ulonglong2 k2 = kp[4 * j + 2], k3 = kp[4 * j + 3];
            fma2(m2[8 * j + 0], k0.x, nu); fma2(m2[8 * j + 1], k0.y, nu);
            fma2(m2[8 * j + 2], k1.x, nu); fma2(m2[8 * j + 3], k1.y, nu);
            fma2(m2[8 * j + 4], k2.x, nu); fma2(m2[8 * j + 5], k2.y, nu);
            fma2(m2[8 * j + 6], k3.x, nu); fma2(m2[8 * j + 7], k3.y, nu);
        }
    }

    // Store final memory half.
    {
        ulonglong2* ob = reinterpret_cast<ulonglong2*>(
            out + (size_t)b * DV * DK + (size_t)r * DK + h * HALF);
        #pragma unroll
        for (int j = 0; j < HALF / 4; ++j) {
            ulonglong2 x;
            x.x = m2[2 * j]; x.y = m2[2 * j + 1];
            ob[j] = x;
        }
    }
}

extern "C" void kernel_launch(void* const* d_in, const int* in_sizes, int n_in,
                              void* d_out, int out_size) {
    const float* memory = (const float*)d_in[0];
    const float* key    = (const float*)d_in[1];
    const float* value  = (const float*)d_in[2];
    float* out = (float*)d_out;

    prep_kernel<<<(BB * SS) / 8, 256>>>(key);
    sgm_kernel<<<BB, 256>>>(memory, value, out);
}